// round 1
// baseline (speedup 1.0000x reference)
#include <cuda_runtime.h>
#include <cstdint>

#define NB 8
#define NN 2048
#define DF 128
#define NF 128

#define BM 128
#define BN 128
#define BK 16

// scratch (no cudaMalloc allowed)
__device__ float g_dinv[NB * NN];
__device__ float g_part[4 * NB * NN];

// ---------------------------------------------------------------------------
// Kernel 1: stream A once: copy to out (if requested) + partial column sums.
// grid: (NN/256, 4 row-chunks, NB), block 256.
// d[b,j] = sum_i A[b,i,j]  (axis=1 of [N,n,n])
// ---------------------------------------------------------------------------
__global__ void __launch_bounds__(256) colsum_copy_kernel(
    const float* __restrict__ A, float* __restrict__ outA)
{
    const int j  = blockIdx.x * 256 + threadIdx.x;
    const int rc = blockIdx.y;
    const int b  = blockIdx.z;
    const float* Ab = A + (size_t)b * NN * NN;
    float s = 0.f;
    const int i0 = rc * (NN / 4);
    if (outA) {
        float* Ob = outA + (size_t)b * NN * NN;
        #pragma unroll 8
        for (int i = i0; i < i0 + NN / 4; ++i) {
            float v = Ab[(size_t)i * NN + j];
            Ob[(size_t)i * NN + j] = v;
            s += v;
        }
    } else {
        #pragma unroll 8
        for (int i = i0; i < i0 + NN / 4; ++i)
            s += Ab[(size_t)i * NN + j];
    }
    g_part[rc * (NB * NN) + b * NN + j] = s;
}

// ---------------------------------------------------------------------------
// Kernel 2: dinv = rsqrt(1 + colsum)   (the +1 is the self-loop / identity)
// ---------------------------------------------------------------------------
__global__ void __launch_bounds__(256) finalize_kernel()
{
    const int idx = blockIdx.x * 256 + threadIdx.x;
    float s = 1.0f + g_part[idx] + g_part[NB * NN + idx]
                   + g_part[2 * NB * NN + idx] + g_part[3 * NB * NN + idx];
    g_dinv[idx] = rsqrtf(s);
}

// ---------------------------------------------------------------------------
// Kernel 3: fused  AY = A @ (dinv*X);  DADH = d_i*AY + d_i^2*X;
//           H = relu(DADH @ W)
// grid: (NN/BM, NB), block 256 (16x16 threads, 8x8 regs each)
// ---------------------------------------------------------------------------
extern __shared__ float smem[];

__global__ void __launch_bounds__(256) gcn_fused_kernel(
    const float* __restrict__ A, const float* __restrict__ X,
    const float* __restrict__ W, float* __restrict__ outH)
{
    const int b     = blockIdx.y;
    const int mBase = blockIdx.x * BM;
    const int tid   = threadIdx.x;
    const int tx    = tid & 15;
    const int ty    = tid >> 4;

    float* sA = smem;             // [BK][BM]  (transposed A tile)
    float* sB = smem + BK * BM;   // [BK][BN]

    const float* Ab = A + (size_t)b * NN * NN + (size_t)mBase * NN;
    const float* Xb = X + (size_t)b * NN * DF;
    const float* dv = g_dinv + b * NN;

    float acc[8][8];
    #pragma unroll
    for (int i = 0; i < 8; ++i)
        #pragma unroll
        for (int j = 0; j < 8; ++j) acc[i][j] = 0.f;

    // loader indexing: A tile 128x16 = 512 float4; B tile 16x128 = 512 float4
    const int ar0 = tid >> 2;            // rows 0..63
    const int ar1 = (tid + 256) >> 2;    // rows 64..127
    const int ac0 = (tid & 3) * 4;       // k-subgroup
    const int bk0 = tid >> 5;            // k rows 0..7 (and +8)
    const int bf  = (tid & 31) * 4;      // feature col

    float4 pa0, pa1, pb0, pb1;
    float  db0, db1;

    // prefetch tile 0
    {
        pa0 = *(const float4*)(Ab + (size_t)ar0 * NN + ac0);
        pa1 = *(const float4*)(Ab + (size_t)ar1 * NN + ac0);
        db0 = dv[bk0];
        db1 = dv[8 + bk0];
        pb0 = *(const float4*)(Xb + (size_t)bk0 * DF + bf);
        pb1 = *(const float4*)(Xb + (size_t)(8 + bk0) * DF + bf);
    }

    for (int k0 = 0; k0 < NN; k0 += BK) {
        // stage registers -> smem
        sA[(ac0 + 0) * BM + ar0] = pa0.x;
        sA[(ac0 + 1) * BM + ar0] = pa0.y;
        sA[(ac0 + 2) * BM + ar0] = pa0.z;
        sA[(ac0 + 3) * BM + ar0] = pa0.w;
        sA[(ac0 + 0) * BM + ar1] = pa1.x;
        sA[(ac0 + 1) * BM + ar1] = pa1.y;
        sA[(ac0 + 2) * BM + ar1] = pa1.z;
        sA[(ac0 + 3) * BM + ar1] = pa1.w;
        float4 q0 = make_float4(pb0.x * db0, pb0.y * db0, pb0.z * db0, pb0.w * db0);
        float4 q1 = make_float4(pb1.x * db1, pb1.y * db1, pb1.z * db1, pb1.w * db1);
        *(float4*)(sB + bk0 * BN + bf)       = q0;
        *(float4*)(sB + (bk0 + 8) * BN + bf) = q1;
        __syncthreads();

        // prefetch next tile (overlaps with compute below)
        if (k0 + BK < NN) {
            const int kn = k0 + BK;
            pa0 = *(const float4*)(Ab + (size_t)ar0 * NN + kn + ac0);
            pa1 = *(const float4*)(Ab + (size_t)ar1 * NN + kn + ac0);
            db0 = dv[kn + bk0];
            db1 = dv[kn + 8 + bk0];
            pb0 = *(const float4*)(Xb + (size_t)(kn + bk0) * DF + bf);
            pb1 = *(const float4*)(Xb + (size_t)(kn + 8 + bk0) * DF + bf);
        }

        #pragma unroll
        for (int kk = 0; kk < BK; ++kk) {
            float4 a0 = *(const float4*)(sA + kk * BM + ty * 8);
            float4 a1 = *(const float4*)(sA + kk * BM + ty * 8 + 4);
            float4 b0 = *(const float4*)(sB + kk * BN + tx * 8);
            float4 b1 = *(const float4*)(sB + kk * BN + tx * 8 + 4);
            float av[8] = {a0.x, a0.y, a0.z, a0.w, a1.x, a1.y, a1.z, a1.w};
            float bv[8] = {b0.x, b0.y, b0.z, b0.w, b1.x, b1.y, b1.z, b1.w};
            #pragma unroll
            for (int i = 0; i < 8; ++i)
                #pragma unroll
                for (int j = 0; j < 8; ++j)
                    acc[i][j] += av[i] * bv[j];
        }
        __syncthreads();
    }

    // ---- epilogue: DADH tile -> smem, W -> smem, H = relu(DADH @ W) ----
    const int LDD = BN + 4;
    float* sD = smem;                   // [BM][LDD]
    float* sW = smem + BM * LDD;        // [DF][NF]

    // cooperative W load (16384 floats)
    for (int idx = tid * 4; idx < DF * NF; idx += 256 * 4)
        *(float4*)(sW + idx) = *(const float4*)(W + idx);

    #pragma unroll
    for (int i = 0; i < 8; ++i) {
        const int r = ty * 8 + i;
        const float di = dv[mBase + r];
        const float dd = di * di;
        const float* xr = Xb + (size_t)(mBase + r) * DF + tx * 8;
        float4 x0 = *(const float4*)(xr);
        float4 x1 = *(const float4*)(xr + 4);
        float4 v0 = make_float4(di * acc[i][0] + dd * x0.x,
                                di * acc[i][1] + dd * x0.y,
                                di * acc[i][2] + dd * x0.z,
                                di * acc[i][3] + dd * x0.w);
        float4 v1 = make_float4(di * acc[i][4] + dd * x1.x,
                                di * acc[i][5] + dd * x1.y,
                                di * acc[i][6] + dd * x1.z,
                                di * acc[i][7] + dd * x1.w);
        *(float4*)(sD + r * LDD + tx * 8)     = v0;
        *(float4*)(sD + r * LDD + tx * 8 + 4) = v1;
    }
    __syncthreads();

    float h[8][8];
    #pragma unroll
    for (int i = 0; i < 8; ++i)
        #pragma unroll
        for (int j = 0; j < 8; ++j) h[i][j] = 0.f;

    for (int c = 0; c < DF; ++c) {
        float4 w0 = *(const float4*)(sW + c * NF + tx * 8);
        float4 w1 = *(const float4*)(sW + c * NF + tx * 8 + 4);
        float bv[8] = {w0.x, w0.y, w0.z, w0.w, w1.x, w1.y, w1.z, w1.w};
        #pragma unroll
        for (int i = 0; i < 8; ++i) {
            float a = sD[(ty * 8 + i) * LDD + c];
            #pragma unroll
            for (int j = 0; j < 8; ++j)
                h[i][j] += a * bv[j];
        }
    }

    float* Hb = outH + (size_t)b * NN * NF + (size_t)mBase * NF;
    #pragma unroll
    for (int i = 0; i < 8; ++i) {
        const int r = ty * 8 + i;
        float4 o0 = make_float4(fmaxf(h[i][0], 0.f), fmaxf(h[i][1], 0.f),
                                fmaxf(h[i][2], 0.f), fmaxf(h[i][3], 0.f));
        float4 o1 = make_float4(fmaxf(h[i][4], 0.f), fmaxf(h[i][5], 0.f),
                                fmaxf(h[i][6], 0.f), fmaxf(h[i][7], 0.f));
        *(float4*)(Hb + (size_t)r * NF + tx * 8)     = o0;
        *(float4*)(Hb + (size_t)r * NF + tx * 8 + 4) = o1;
    }
}

// ---------------------------------------------------------------------------
extern "C" void kernel_launch(void* const* d_in, const int* in_sizes, int n_in,
                              void* d_out, int out_size)
{
    const float* A = (const float*)d_in[0];
    const float* X = (const float*)d_in[1];
    const float* W = (const float*)d_in[2];
    float* out = (float*)d_out;

    const long long A_ELEMS = (long long)NB * NN * NN;
    const long long H_ELEMS = (long long)NB * NN * NF;

    float* outA = nullptr;
    float* outH = out;
    if ((long long)out_size >= A_ELEMS + H_ELEMS) {
        // output tuple (A, H): A first, H last
        outA = out;
        outH = out + ((long long)out_size - H_ELEMS);
    }

    const size_t smemBytes = (size_t)(BM * (BN + 4) + DF * NF) * sizeof(float);
    cudaFuncSetAttribute(gcn_fused_kernel,
                         cudaFuncAttributeMaxDynamicSharedMemorySize,
                         (int)smemBytes);

    dim3 g1(NN / 256, 4, NB);
    colsum_copy_kernel<<<g1, 256>>>(A, outA);

    finalize_kernel<<<(NB * NN) / 256, 256>>>();

    dim3 g3(NN / BM, NB);
    gcn_fused_kernel<<<g3, 256, smemBytes>>>(A, X, W, outH);
}

// round 7
// speedup vs baseline: 2.6459x; 2.6459x over previous
#include <cuda_runtime.h>
#include <cstdint>

#define NB 8
#define NN 2048
#define DF 128
#define NF 128

// ---------------- scratch (no cudaMalloc allowed) ----------------
__device__ __align__(16) float g_Y[NB * NN * DF];    // tf32(dinv[k]*X[k][f]), row-major
__device__ float g_dinv[NB * NN];
__device__ __align__(16) float g_part[32 * NB * NN];

// ---------------- helpers ----------------
__device__ __forceinline__ uint32_t smem_u32(const void* p) {
    uint32_t a;
    asm("{ .reg .u64 t; cvta.to.shared.u64 t, %1; cvt.u32.u64 %0, t; }" : "=r"(a) : "l"(p));
    return a;
}
__device__ __forceinline__ uint32_t f2tf(float f) {
    uint32_t u; asm("cvt.rna.tf32.f32 %0, %1;" : "=r"(u) : "f"(f)); return u;
}

#define CPA16(dst, src) \
    asm volatile("cp.async.cg.shared.global [%0], [%1], 16;" :: "r"(dst), "l"(src))
#define CPA_COMMIT() asm volatile("cp.async.commit_group;" ::: "memory")
#define CPA_WAIT(n)  asm volatile("cp.async.wait_group %0;" :: "n"(n) : "memory")

#define MMA_TF32(c, a, bq) \
    asm volatile("mma.sync.aligned.m16n8k8.row.col.f32.tf32.tf32.f32 " \
        "{%0,%1,%2,%3}, {%4,%5,%6,%7}, {%8,%9}, {%0,%1,%2,%3};" \
        : "+f"((c)[0]), "+f"((c)[1]), "+f"((c)[2]), "+f"((c)[3]) \
        : "r"((a)[0]), "r"((a)[1]), "r"((a)[2]), "r"((a)[3]), \
          "r"((bq)[0]), "r"((bq)[1]))

// ---------------- Kernel 1: column sums + copy A to out ----------------
__global__ void __launch_bounds__(256) colsum_copy_kernel(
    const float* __restrict__ A, float* __restrict__ outA)
{
    const int j4 = blockIdx.x * 256 + threadIdx.x;   // float4 col, 0..511
    const int rc = blockIdx.y;                        // 0..31
    const int b  = blockIdx.z;
    const float4* Ab = (const float4*)(A + (size_t)b * NN * NN);
    float4 s = make_float4(0.f, 0.f, 0.f, 0.f);
    const int i0 = rc * (NN / 32);
    if (outA) {
        float4* Ob = (float4*)(outA + (size_t)b * NN * NN);
        #pragma unroll 8
        for (int i = i0; i < i0 + NN / 32; ++i) {
            float4 v = Ab[(size_t)i * (NN / 4) + j4];
            Ob[(size_t)i * (NN / 4) + j4] = v;
            s.x += v.x; s.y += v.y; s.z += v.z; s.w += v.w;
        }
    } else {
        #pragma unroll 8
        for (int i = i0; i < i0 + NN / 32; ++i) {
            float4 v = Ab[(size_t)i * (NN / 4) + j4];
            s.x += v.x; s.y += v.y; s.z += v.z; s.w += v.w;
        }
    }
    *(float4*)(g_part + (size_t)rc * (NB * NN) + b * NN + j4 * 4) = s;
}

// ---------------- Kernel 2: dinv = rsqrt(1 + colsum) ----------------
__global__ void __launch_bounds__(256) finalize_kernel()
{
    const int idx = blockIdx.x * 256 + threadIdx.x;
    float s = 1.0f;
    #pragma unroll
    for (int rc = 0; rc < 32; ++rc) s += g_part[rc * (NB * NN) + idx];
    g_dinv[idx] = rsqrtf(s);
}

// ---------------- Kernel 3: Y = tf32(dinv[k] * X[k][f]) ----------------
__global__ void __launch_bounds__(256) scale_cvt_kernel(const float* __restrict__ X)
{
    const int idx = blockIdx.x * 256 + threadIdx.x;   // float4 index
    const int e = idx << 2;
    const int b = e >> 18;               // NN*DF = 2^18
    const int k = (e >> 7) & (NN - 1);   // DF = 2^7
    const float d = g_dinv[b * NN + k];
    float4 x = *(const float4*)(X + (size_t)e);
    uint4 y;
    y.x = f2tf(d * x.x); y.y = f2tf(d * x.y);
    y.z = f2tf(d * x.z); y.w = f2tf(d * x.w);
    *(uint4*)(g_Y + (size_t)e) = y;
}

// ---------------- Kernel 4: fused tf32 mma.sync GEMM ----------------
// block tile 128(M) x 128(N), K-step 32, 8 warps (2M x 4N), warp tile 64x32.
#define LDA 36
#define LDB 136
#define LDW 136
#define LDD 132
#define SA_FLOATS (2 * 128 * LDA)     // 9216
#define SB_FLOATS (2 * 32 * LDB)      // 8704
#define SW_FLOATS (128 * LDW)         // 17408
#define SMEM_TOTAL ((SA_FLOATS + SB_FLOATS + SW_FLOATS) * 4)   // 141312 B

__global__ void __launch_bounds__(256, 1) gcn_mma_kernel(
    const float* __restrict__ A, const float* __restrict__ X,
    const float* __restrict__ W, float* __restrict__ outH)
{
    extern __shared__ float sm[];
    float* sA = sm;                          // [2][128][LDA]
    float* sB = sm + SA_FLOATS;              // [2][32][LDB]
    float* sW = sm + SA_FLOATS + SB_FLOATS;  // [128][LDW]
    float* sD = sm;                          // reuse as [128][LDD] after main loop

    const uint32_t smbA = smem_u32(sA);
    const uint32_t smbB = smem_u32(sB);

    const int tid  = threadIdx.x;
    const int wid  = tid >> 5;
    const int lane = tid & 31;
    const int b     = blockIdx.y;
    const int mBase = blockIdx.x * 128;
    const int warpM = (wid >> 2) * 64;     // 0 or 64
    const int warpN = (wid & 3) * 32;      // 0,32,64,96
    const int gr = lane >> 2;              // 0..7
    const int gc = lane & 3;               // 0..3

    const float* Ab = A + (size_t)b * NN * NN + (size_t)mBase * NN;
    const float* Yb = g_Y + (size_t)b * NN * DF;

    // ---- W -> sW (tf32-converted), once ----
    for (int i = tid; i < 128 * 32; i += 256) {   // 4096 float4 chunks
        int d = i >> 5, f4 = (i & 31) << 2;
        float4 w = *(const float4*)(W + d * NF + f4);
        uint4 u;
        u.x = f2tf(w.x); u.y = f2tf(w.y); u.z = f2tf(w.z); u.w = f2tf(w.w);
        *(uint4*)(sW + d * LDW + f4) = u;
    }

    float acc[4][4][4];
    #pragma unroll
    for (int mf = 0; mf < 4; ++mf)
        #pragma unroll
        for (int nf = 0; nf < 4; ++nf)
            #pragma unroll
            for (int q = 0; q < 4; ++q) acc[mf][nf][q] = 0.f;

    // cp.async stage loader: A 128x32, B 32x128 (Y row-major, pre-tf32)
    auto load_stage = [&](int st, int k0) {
        #pragma unroll
        for (int t = 0; t < 4; ++t) {
            int c = t * 256 + tid;
            int row = c >> 3, col4 = (c & 7) << 2;
            CPA16(smbA + ((st * 128 * LDA + row * LDA + col4) << 2),
                  Ab + (size_t)row * NN + k0 + col4);
        }
        #pragma unroll
        for (int t = 0; t < 4; ++t) {
            int c = t * 256 + tid;
            int row = c >> 5, col4 = (c & 31) << 2;
            CPA16(smbB + ((st * 32 * LDB + row * LDB + col4) << 2),
                  Yb + (size_t)(k0 + row) * DF + col4);
        }
    };

    load_stage(0, 0);
    CPA_COMMIT();

    for (int c = 0; c < NN / 32; ++c) {
        const int st = c & 1;
        if (c + 1 < NN / 32) {
            load_stage((c + 1) & 1, (c + 1) * 32);
            CPA_COMMIT();
            CPA_WAIT(1);
        } else {
            CPA_WAIT(0);
        }
        __syncthreads();

        const float* pA = sA + st * 128 * LDA;
        const float* pB = sB + st * 32 * LDB;
        #pragma unroll
        for (int ks = 0; ks < 4; ++ks) {
            const int kc = ks * 8 + gc;
            uint32_t aF[4][4], bF[4][2];
            #pragma unroll
            for (int mf = 0; mf < 4; ++mf) {
                int r = warpM + mf * 16 + gr;
                aF[mf][0] = f2tf(pA[r * LDA + kc]);
                aF[mf][1] = f2tf(pA[(r + 8) * LDA + kc]);
                aF[mf][2] = f2tf(pA[r * LDA + kc + 4]);
                aF[mf][3] = f2tf(pA[(r + 8) * LDA + kc + 4]);
            }
            #pragma unroll
            for (int nf = 0; nf < 4; ++nf) {
                int n = warpN + nf * 8 + gr;
                bF[nf][0] = __float_as_uint(pB[kc * LDB + n]);
                bF[nf][1] = __float_as_uint(pB[(kc + 4) * LDB + n]);
            }
            #pragma unroll
            for (int mf = 0; mf < 4; ++mf)
                #pragma unroll
                for (int nf = 0; nf < 4; ++nf)
                    MMA_TF32(acc[mf][nf], aF[mf], bF[nf]);
        }
        __syncthreads();
    }

    // ---- epilogue 1: DADH = d_i*acc + d_i^2*X -> sD (tf32-converted) ----
    const float* Xb = X + (size_t)b * NN * DF;
    #pragma unroll
    for (int mf = 0; mf < 4; ++mf) {
        const int r0 = warpM + mf * 16 + gr;       // local row
        const int g0 = mBase + r0;                  // global row
        const float d0 = g_dinv[b * NN + g0];
        const float d1 = g_dinv[b * NN + g0 + 8];
        #pragma unroll
        for (int nf = 0; nf < 4; ++nf) {
            const int col = warpN + nf * 8 + 2 * gc;
            float2 x0 = *(const float2*)(Xb + (size_t)g0 * DF + col);
            float2 x1 = *(const float2*)(Xb + (size_t)(g0 + 8) * DF + col);
            uint32_t v00 = f2tf(d0 * acc[mf][nf][0] + d0 * d0 * x0.x);
            uint32_t v01 = f2tf(d0 * acc[mf][nf][1] + d0 * d0 * x0.y);
            uint32_t v10 = f2tf(d1 * acc[mf][nf][2] + d1 * d1 * x1.x);
            uint32_t v11 = f2tf(d1 * acc[mf][nf][3] + d1 * d1 * x1.y);
            *(uint2*)(sD + r0 * LDD + col)       = make_uint2(v00, v01);
            *(uint2*)(sD + (r0 + 8) * LDD + col) = make_uint2(v10, v11);
        }
    }
    __syncthreads();

    // ---- epilogue 2: H = relu(DADH @ W), K = 128 ----
    float h[4][4][4];
    #pragma unroll
    for (int mf = 0; mf < 4; ++mf)
        #pragma unroll
        for (int nf = 0; nf < 4; ++nf)
            #pragma unroll
            for (int q = 0; q < 4; ++q) h[mf][nf][q] = 0.f;

    #pragma unroll
    for (int ks = 0; ks < 16; ++ks) {
        const int kc = ks * 8 + gc;
        uint32_t aF[4][4], bF[4][2];
        #pragma unroll
        for (int mf = 0; mf < 4; ++mf) {
            int r = warpM + mf * 16 + gr;
            aF[mf][0] = __float_as_uint(sD[r * LDD + kc]);
            aF[mf][1] = __float_as_uint(sD[(r + 8) * LDD + kc]);
            aF[mf][2] = __float_as_uint(sD[r * LDD + kc + 4]);
            aF[mf][3] = __float_as_uint(sD[(r + 8) * LDD + kc + 4]);
        }
        #pragma unroll
        for (int nf = 0; nf < 4; ++nf) {
            int n = warpN + nf * 8 + gr;
            bF[nf][0] = __float_as_uint(sW[kc * LDW + n]);
            bF[nf][1] = __float_as_uint(sW[(kc + 4) * LDW + n]);
        }
        #pragma unroll
        for (int mf = 0; mf < 4; ++mf)
            #pragma unroll
            for (int nf = 0; nf < 4; ++nf)
                MMA_TF32(h[mf][nf], aF[mf], bF[nf]);
    }

    // ---- relu + store ----
    float* Hb = outH + (size_t)b * NN * NF;
    #pragma unroll
    for (int mf = 0; mf < 4; ++mf) {
        const int g0 = mBase + warpM + mf * 16 + gr;
        #pragma unroll
        for (int nf = 0; nf < 4; ++nf) {
            const int col = warpN + nf * 8 + 2 * gc;
            float2 o0 = make_float2(fmaxf(h[mf][nf][0], 0.f), fmaxf(h[mf][nf][1], 0.f));
            float2 o1 = make_float2(fmaxf(h[mf][nf][2], 0.f), fmaxf(h[mf][nf][3], 0.f));
            *(float2*)(Hb + (size_t)g0 * NF + col)       = o0;
            *(float2*)(Hb + (size_t)(g0 + 8) * NF + col) = o1;
        }
    }
}

// ---------------- host ----------------
extern "C" void kernel_launch(void* const* d_in, const int* in_sizes, int n_in,
                              void* d_out, int out_size)
{
    const float* A = (const float*)d_in[0];
    const float* X = (const float*)d_in[1];
    const float* W = (const float*)d_in[2];
    float* out = (float*)d_out;

    const long long A_ELEMS = (long long)NB * NN * NN;
    const long long H_ELEMS = (long long)NB * NN * NF;
    float* outA = nullptr;
    float* outH = out;
    if ((long long)out_size >= A_ELEMS + H_ELEMS) {
        outA = out;
        outH = out + ((long long)out_size - H_ELEMS);
    }

    cudaFuncSetAttribute(gcn_mma_kernel,
                         cudaFuncAttributeMaxDynamicSharedMemorySize, SMEM_TOTAL);

    dim3 g1(2, 32, NB);
    colsum_copy_kernel<<<g1, 256>>>(A, outA);

    finalize_kernel<<<(NB * NN) / 256, 256>>>();

    scale_cvt_kernel<<<(NB * NN * DF / 4) / 256, 256>>>(X);

    dim3 g4(NN / 128, NB);
    gcn_mma_kernel<<<g4, 256, SMEM_TOTAL>>>(A, X, W, outH);
}

// round 12
// speedup vs baseline: 2.7550x; 1.0413x over previous
#include <cuda_runtime.h>
#include <cstdint>

#define NB 8
#define NN 2048
#define DF 128
#define NF 128

// ---------------- scratch (no cudaMalloc allowed) ----------------
__device__ __align__(16) float g_Y[NB * NN * DF];    // tf32(dinv[k]*X[k][f]), row-major
__device__ float g_dinv[NB * NN];
__device__ __align__(16) float g_part[32 * NB * NN];

// ---------------- helpers ----------------
__device__ __forceinline__ uint32_t smem_u32(const void* p) {
    uint32_t a;
    asm("{ .reg .u64 t; cvta.to.shared.u64 t, %1; cvt.u32.u64 %0, t; }" : "=r"(a) : "l"(p));
    return a;
}
__device__ __forceinline__ uint32_t f2tf(float f) {
    uint32_t u; asm("cvt.rna.tf32.f32 %0, %1;" : "=r"(u) : "f"(f)); return u;
}

#define CPA16(dst, src) \
    asm volatile("cp.async.cg.shared.global [%0], [%1], 16;" :: "r"(dst), "l"(src))
#define CPA_COMMIT() asm volatile("cp.async.commit_group;" ::: "memory")
#define CPA_WAIT(n)  asm volatile("cp.async.wait_group %0;" :: "n"(n) : "memory")

#define MMA_TF32(c, a, bq) \
    asm volatile("mma.sync.aligned.m16n8k8.row.col.f32.tf32.tf32.f32 " \
        "{%0,%1,%2,%3}, {%4,%5,%6,%7}, {%8,%9}, {%0,%1,%2,%3};" \
        : "+f"((c)[0]), "+f"((c)[1]), "+f"((c)[2]), "+f"((c)[3]) \
        : "r"((a)[0]), "r"((a)[1]), "r"((a)[2]), "r"((a)[3]), \
          "r"((bq)[0]), "r"((bq)[1]))

// ---------------- Kernel 1: column sums + copy A to out ----------------
__global__ void __launch_bounds__(256) colsum_copy_kernel(
    const float* __restrict__ A, float* __restrict__ outA)
{
    const int j4 = blockIdx.x * 256 + threadIdx.x;   // float4 col, 0..511
    const int rc = blockIdx.y;                        // 0..31
    const int b  = blockIdx.z;
    const float4* Ab = (const float4*)(A + (size_t)b * NN * NN);
    float4 s = make_float4(0.f, 0.f, 0.f, 0.f);
    const int i0 = rc * (NN / 32);
    if (outA) {
        float4* Ob = (float4*)(outA + (size_t)b * NN * NN);
        #pragma unroll 8
        for (int i = i0; i < i0 + NN / 32; ++i) {
            float4 v = Ab[(size_t)i * (NN / 4) + j4];
            Ob[(size_t)i * (NN / 4) + j4] = v;
            s.x += v.x; s.y += v.y; s.z += v.z; s.w += v.w;
        }
    } else {
        #pragma unroll 8
        for (int i = i0; i < i0 + NN / 32; ++i) {
            float4 v = Ab[(size_t)i * (NN / 4) + j4];
            s.x += v.x; s.y += v.y; s.z += v.z; s.w += v.w;
        }
    }
    *(float4*)(g_part + (size_t)rc * (NB * NN) + b * NN + j4 * 4) = s;
}

// ---------------- Kernel 2: dinv = rsqrt(1 + colsum) ----------------
__global__ void __launch_bounds__(256) finalize_kernel()
{
    const int idx = blockIdx.x * 256 + threadIdx.x;
    float s = 1.0f;
    #pragma unroll
    for (int rc = 0; rc < 32; ++rc) s += g_part[rc * (NB * NN) + idx];
    g_dinv[idx] = rsqrtf(s);
}

// ---------------- Kernel 3: Y = tf32(dinv[k] * X[k][f]) ----------------
__global__ void __launch_bounds__(256) scale_cvt_kernel(const float* __restrict__ X)
{
    const int idx = blockIdx.x * 256 + threadIdx.x;   // float4 index
    const int e = idx << 2;
    const int b = e >> 18;               // NN*DF = 2^18
    const int k = (e >> 7) & (NN - 1);   // DF = 2^7
    const float d = g_dinv[b * NN + k];
    float4 x = *(const float4*)(X + (size_t)e);
    uint4 y;
    y.x = f2tf(d * x.x); y.y = f2tf(d * x.y);
    y.z = f2tf(d * x.z); y.w = f2tf(d * x.w);
    *(uint4*)(g_Y + (size_t)e) = y;
}

// ---------------- Kernel 4: fused tf32 mma.sync GEMM ----------------
// block tile 64(M) x 128(N), K-step 32, 8 warps (2M x 4N), warp tile 32x32.
// 2 CTAs/SM (103KB smem each).
#define LDA 36
#define LDB 136
#define LDW 136
#define LDD 132
#define SA_FLOATS (2 * 64 * LDA)      // 4608
#define SB_FLOATS (2 * 32 * LDB)      // 8704
#define SD_FLOATS (64 * LDD)          // 8448
#define SW_OFF    SD_FLOATS           // W region starts after sD
#define SMEM_FLOATS (SW_OFF + 128 * LDW)   // 8448 + 17408 = 25856
#define SMEM_TOTAL (SMEM_FLOATS * 4)       // 103424 B

__global__ void __launch_bounds__(256, 2) gcn_mma_kernel(
    const float* __restrict__ A, const float* __restrict__ X,
    const float* __restrict__ W, float* __restrict__ outH)
{
    extern __shared__ float sm[];
    float* sA = sm;                          // [2][64][LDA]   (main loop)
    float* sB = sm + SA_FLOATS;              // [2][32][LDB]   (main loop)
    float* sD = sm;                          // [64][LDD]      (epilogue, reuses stages)
    float* sW = sm + SW_OFF;                 // [128][LDW]     (epilogue)

    const uint32_t smbA = smem_u32(sA);
    const uint32_t smbB = smem_u32(sB);

    const int tid  = threadIdx.x;
    const int wid  = tid >> 5;
    const int lane = tid & 31;
    const int b     = blockIdx.y;
    const int mBase = blockIdx.x * 64;
    const int warpM = (wid >> 2) * 32;     // 0 or 32
    const int warpN = (wid & 3) * 32;      // 0,32,64,96
    const int gr = lane >> 2;              // 0..7
    const int gc = lane & 3;               // 0..3

    const float* Ab = A + (size_t)b * NN * NN + (size_t)mBase * NN;
    const float* Yb = g_Y + (size_t)b * NN * DF;

    float acc[2][4][4];
    #pragma unroll
    for (int mf = 0; mf < 2; ++mf)
        #pragma unroll
        for (int nf = 0; nf < 4; ++nf)
            #pragma unroll
            for (int q = 0; q < 4; ++q) acc[mf][nf][q] = 0.f;

    // cp.async stage loader: A 64x32 (512 float4), B 32x128 (1024 float4)
    auto load_stage = [&](int st, int k0) {
        #pragma unroll
        for (int t = 0; t < 2; ++t) {
            int c = t * 256 + tid;
            int row = c >> 3, col4 = (c & 7) << 2;
            CPA16(smbA + ((st * 64 * LDA + row * LDA + col4) << 2),
                  Ab + (size_t)row * NN + k0 + col4);
        }
        #pragma unroll
        for (int t = 0; t < 4; ++t) {
            int c = t * 256 + tid;
            int row = c >> 5, col4 = (c & 31) << 2;
            CPA16(smbB + ((st * 32 * LDB + row * LDB + col4) << 2),
                  Yb + (size_t)(k0 + row) * DF + col4);
        }
    };

    load_stage(0, 0);
    CPA_COMMIT();

    for (int c = 0; c < NN / 32; ++c) {
        const int st = c & 1;
        if (c + 1 < NN / 32) {
            load_stage((c + 1) & 1, (c + 1) * 32);
            CPA_COMMIT();
            CPA_WAIT(1);
        } else {
            CPA_WAIT(0);
        }
        __syncthreads();

        const float* pA = sA + st * 64 * LDA;
        const float* pB = sB + st * 32 * LDB;
        #pragma unroll
        for (int ks = 0; ks < 4; ++ks) {
            const int kc = ks * 8 + gc;
            uint32_t aF[2][4], bF[4][2];
            #pragma unroll
            for (int mf = 0; mf < 2; ++mf) {
                int r = warpM + mf * 16 + gr;
                aF[mf][0] = f2tf(pA[r * LDA + kc]);
                aF[mf][1] = f2tf(pA[(r + 8) * LDA + kc]);
                aF[mf][2] = f2tf(pA[r * LDA + kc + 4]);
                aF[mf][3] = f2tf(pA[(r + 8) * LDA + kc + 4]);
            }
            #pragma unroll
            for (int nf = 0; nf < 4; ++nf) {
                int n = warpN + nf * 8 + gr;
                bF[nf][0] = __float_as_uint(pB[kc * LDB + n]);
                bF[nf][1] = __float_as_uint(pB[(kc + 4) * LDB + n]);
            }
            #pragma unroll
            for (int mf = 0; mf < 2; ++mf)
                #pragma unroll
                for (int nf = 0; nf < 4; ++nf)
                    MMA_TF32(acc[mf][nf], aF[mf], bF[nf]);
        }
        __syncthreads();
    }

    // ---- epilogue 1: DADH = d_i*acc + d_i^2*X -> sD (tf32) ; also load W -> sW ----
    const float* Xb = X + (size_t)b * NN * DF;
    #pragma unroll
    for (int mf = 0; mf < 2; ++mf) {
        const int r0 = warpM + mf * 16 + gr;       // local row 0..63
        const int g0 = mBase + r0;                  // global row
        const float d0 = g_dinv[b * NN + g0];
        const float d1 = g_dinv[b * NN + g0 + 8];
        #pragma unroll
        for (int nf = 0; nf < 4; ++nf) {
            const int col = warpN + nf * 8 + 2 * gc;
            float2 x0 = *(const float2*)(Xb + (size_t)g0 * DF + col);
            float2 x1 = *(const float2*)(Xb + (size_t)(g0 + 8) * DF + col);
            uint32_t v00 = f2tf(d0 * acc[mf][nf][0] + d0 * d0 * x0.x);
            uint32_t v01 = f2tf(d0 * acc[mf][nf][1] + d0 * d0 * x0.y);
            uint32_t v10 = f2tf(d1 * acc[mf][nf][2] + d1 * d1 * x1.x);
            uint32_t v11 = f2tf(d1 * acc[mf][nf][3] + d1 * d1 * x1.y);
            *(uint2*)(sD + r0 * LDD + col)       = make_uint2(v00, v01);
            *(uint2*)(sD + (r0 + 8) * LDD + col) = make_uint2(v10, v11);
        }
    }
    // W -> sW (tf32), cooperative; L2-hot after first CTAs
    for (int i = tid; i < 128 * 32; i += 256) {
        int d = i >> 5, f4 = (i & 31) << 2;
        float4 w = *(const float4*)(W + d * NF + f4);
        uint4 u;
        u.x = f2tf(w.x); u.y = f2tf(w.y); u.z = f2tf(w.z); u.w = f2tf(w.w);
        *(uint4*)(sW + d * LDW + f4) = u;
    }
    __syncthreads();

    // ---- epilogue 2: H = relu(DADH @ W), K = 128 ----
    float h[2][4][4];
    #pragma unroll
    for (int mf = 0; mf < 2; ++mf)
        #pragma unroll
        for (int nf = 0; nf < 4; ++nf)
            #pragma unroll
            for (int q = 0; q < 4; ++q) h[mf][nf][q] = 0.f;

    #pragma unroll
    for (int ks = 0; ks < 16; ++ks) {
        const int kc = ks * 8 + gc;
        uint32_t aF[2][4], bF[4][2];
        #pragma unroll
        for (int mf = 0; mf < 2; ++mf) {
            int r = warpM + mf * 16 + gr;
            aF[mf][0] = __float_as_uint(sD[r * LDD + kc]);
            aF[mf][1] = __float_as_uint(sD[(r + 8) * LDD + kc]);
            aF[mf][2] = __float_as_uint(sD[r * LDD + kc + 4]);
            aF[mf][3] = __float_as_uint(sD[(r + 8) * LDD + kc + 4]);
        }
        #pragma unroll
        for (int nf = 0; nf < 4; ++nf) {
            int n = warpN + nf * 8 + gr;
            bF[nf][0] = __float_as_uint(sW[kc * LDW + n]);
            bF[nf][1] = __float_as_uint(sW[(kc + 4) * LDW + n]);
        }
        #pragma unroll
        for (int mf = 0; mf < 2; ++mf)
            #pragma unroll
            for (int nf = 0; nf < 4; ++nf)
                MMA_TF32(h[mf][nf], aF[mf], bF[nf]);
    }

    // ---- relu + store ----
    float* Hb = outH + (size_t)b * NN * NF;
    #pragma unroll
    for (int mf = 0; mf < 2; ++mf) {
        const int g0 = mBase + warpM + mf * 16 + gr;
        #pragma unroll
        for (int nf = 0; nf < 4; ++nf) {
            const int col = warpN + nf * 8 + 2 * gc;
            float2 o0 = make_float2(fmaxf(h[mf][nf][0], 0.f), fmaxf(h[mf][nf][1], 0.f));
            float2 o1 = make_float2(fmaxf(h[mf][nf][2], 0.f), fmaxf(h[mf][nf][3], 0.f));
            *(float2*)(Hb + (size_t)g0 * NF + col)       = o0;
            *(float2*)(Hb + (size_t)(g0 + 8) * NF + col) = o1;
        }
    }
}

// ---------------- host ----------------
extern "C" void kernel_launch(void* const* d_in, const int* in_sizes, int n_in,
                              void* d_out, int out_size)
{
    const float* A = (const float*)d_in[0];
    const float* X = (const float*)d_in[1];
    const float* W = (const float*)d_in[2];
    float* out = (float*)d_out;

    const long long A_ELEMS = (long long)NB * NN * NN;
    const long long H_ELEMS = (long long)NB * NN * NF;
    float* outA = nullptr;
    float* outH = out;
    if ((long long)out_size >= A_ELEMS + H_ELEMS) {
        outA = out;
        outH = out + ((long long)out_size - H_ELEMS);
    }

    cudaFuncSetAttribute(gcn_mma_kernel,
                         cudaFuncAttributeMaxDynamicSharedMemorySize, SMEM_TOTAL);

    dim3 g1(2, 32, NB);
    colsum_copy_kernel<<<g1, 256>>>(A, outA);

    finalize_kernel<<<(NB * NN) / 256, 256>>>();

    scale_cvt_kernel<<<(NB * NN * DF / 4) / 256, 256>>>(X);

    dim3 g4(NN / 64, NB);
    gcn_mma_kernel<<<g4, 256, SMEM_TOTAL>>>(A, X, W, outH);
}